// round 13
// baseline (speedup 1.0000x reference)
#include <cuda_runtime.h>
#include <math.h>
#include <stdint.h>

// RoPE: X (L=2048, D=4096, N=4) fp32, row-major.
// out[:, :half]  = cos*x1 - sin*x2 ; out[:, half:] = sin*x1 + cos*x2
// theta_i = 10000^(i/2048), ang = (l+1)*theta_i  (fp32 in the reference)
//
// ROOFLINE-FINAL. 268 MB/iter of mandated fp32 traffic crosses the L2
// fabric at the B300 LTS cap (~6300 B/cyc, path-independent) -> ~42.8us
// kernel floor. Verified invariant across occupancy (40-88%), MLP (2-8),
// access width (128/256b), cache policy (default/.cs/evict_last), and
// persistent-vs-oversubscribed scheduling. Best-measured configuration:
// grid=4096 x 256, G=4 l-values/thread, float4 .cs streaming both ways,
// 8 front-batched loads. theta rebuilt per-thread as a double-float
// product of host constants c_k = 10000^(2^k/2048) (rounds identically
// to double pow); exact fp64 range reduction of the fp32 angle; sincosf.

#define L_DIM 2048
#define D4    4096      // float4s per l-row
#define HALF  2048
#define G     4         // l-values per thread

struct ThetaC { float hi[11]; float lo[11]; };

__device__ __forceinline__ float4 ld_stream(const float4* p) {
    float4 v;
    asm volatile("ld.global.cs.v4.f32 {%0,%1,%2,%3}, [%4];"
                 : "=f"(v.x), "=f"(v.y), "=f"(v.z), "=f"(v.w) : "l"(p));
    return v;
}
__device__ __forceinline__ void st_stream(float4* p, float4 v) {
    asm volatile("st.global.cs.v4.f32 [%0], {%1,%2,%3,%4};"
                 :: "l"(p), "f"(v.x), "f"(v.y), "f"(v.z), "f"(v.w));
}

__global__ __launch_bounds__(256)
void rope_kernel(const float4* __restrict__ X, float4* __restrict__ out, ThetaC tc) {
    int t  = blockIdx.x * blockDim.x + threadIdx.x;   // 0 .. (L/G)*HALF - 1
    int i  = t & (HALF - 1);                          // rotary index
    int l0 = (t >> 11) * G;                           // first l for this thread

    // ---- front-batched streaming loads (MLP = 8) ------------------------
    int base = l0 * D4 + i;
    float4 x1[G], x2[G];
    #pragma unroll
    for (int k = 0; k < G; k++) {
        x1[k] = ld_stream(&X[base + k * D4]);
        x2[k] = ld_stream(&X[base + k * D4 + HALF]);
    }

    // ---- double-float theta = prod_{bit k of i} c_k ----------------------
    float th = 1.0f, tl = 0.0f;
    #pragma unroll
    for (int k = 0; k < 11; k++) {
        if (i & (1 << k)) {
            float bh = tc.hi[k], bl = tc.lo[k];
            float p  = th * bh;
            float e  = fmaf(th, bh, -p);
            e        = fmaf(th, bl, e);
            e        = fmaf(tl, bh, e);
            float s  = p + e;
            tl       = (p - s) + e;
            th       = s;
        }
    }
    float theta = th + tl;   // correctly-rounded fp32 theta

    // ---- rotate + streaming stores ----------------------------------------
    #pragma unroll
    for (int k = 0; k < G; k++) {
        // exactly one fp32 multiply, as in the reference
        float ang = (float)(l0 + k + 1) * theta;

        // exact-angle range reduction in double (|ang| < 2.1e7 << 2^53)
        double ad = (double)ang;
        double q  = rint(ad * 0.15915494309189535);          // 1/(2*pi)
        float  r  = (float)fma(q, -6.283185307179586, ad);   // |r| <= pi

        float s, c;
        sincosf(r, &s, &c);   // fast polynomial path on [-pi, pi]

        float4 a = x1[k], b = x2[k], o1, o2;
        o1.x = c * a.x - s * b.x;  o1.y = c * a.y - s * b.y;
        o1.z = c * a.z - s * b.z;  o1.w = c * a.w - s * b.w;
        o2.x = s * a.x + c * b.x;  o2.y = s * a.y + c * b.y;
        o2.z = s * a.z + c * b.z;  o2.w = s * a.w + c * b.w;

        st_stream(&out[base + k * D4],        o1);
        st_stream(&out[base + k * D4 + HALF], o2);
    }
}

extern "C" void kernel_launch(void* const* d_in, const int* in_sizes, int n_in,
                              void* d_out, int out_size) {
    const float4* X   = (const float4*)d_in[0];
    float4*       out = (float4*)d_out;

    ThetaC tc;
    for (int k = 0; k < 11; k++) {
        double c = pow(10000.0, (double)(1 << k) / 2048.0);
        tc.hi[k] = (float)c;
        tc.lo[k] = (float)(c - (double)tc.hi[k]);
    }

    int total = (L_DIM / G) * HALF;           // 1,048,576 threads
    rope_kernel<<<total / 256, 256>>>(X, out, tc);
}

// round 14
// speedup vs baseline: 1.0085x; 1.0085x over previous
#include <cuda_runtime.h>
#include <math.h>
#include <stdint.h>

// RoPE: X (L=2048, D=4096, N=4) fp32, row-major.
// out[:, :half]  = cos*x1 - sin*x2 ; out[:, half:] = sin*x1 + cos*x2
// theta_i = 10000^(i/2048), ang = (l+1)*theta_i  (fp32 in the reference)
//
// At the memory-fabric roofline: 268 MB/iter mandated fp32 traffic at the
// chip's mixed-R/W ceiling (~6.26 TB/s L2-side) -> ~42.8us kernel floor,
// invariant across 9 structural variants. This round samples the last
// untried interior point: G=2 l-values/thread (MLP=4, ~64-75% occupancy,
// between the G=1/88% and G=4/46% plateau points). float4 .cs streaming
// both ways; double-float theta from host constants c_k = 10000^(2^k/2048);
// exact fp64 range reduction of the fp32 angle; sincosf.

#define L_DIM 2048
#define D4    4096      // float4s per l-row
#define HALF  2048
#define G     2         // l-values per thread

struct ThetaC { float hi[11]; float lo[11]; };

__device__ __forceinline__ float4 ld_stream(const float4* p) {
    float4 v;
    asm volatile("ld.global.cs.v4.f32 {%0,%1,%2,%3}, [%4];"
                 : "=f"(v.x), "=f"(v.y), "=f"(v.z), "=f"(v.w) : "l"(p));
    return v;
}
__device__ __forceinline__ void st_stream(float4* p, float4 v) {
    asm volatile("st.global.cs.v4.f32 [%0], {%1,%2,%3,%4};"
                 :: "l"(p), "f"(v.x), "f"(v.y), "f"(v.z), "f"(v.w));
}

__global__ __launch_bounds__(256)
void rope_kernel(const float4* __restrict__ X, float4* __restrict__ out, ThetaC tc) {
    int t  = blockIdx.x * blockDim.x + threadIdx.x;   // 0 .. (L/G)*HALF - 1
    int i  = t & (HALF - 1);                          // rotary index
    int l0 = (t >> 11) * G;                           // first l for this thread

    // ---- front-batched streaming loads (MLP = 4) ------------------------
    int base = l0 * D4 + i;
    float4 x1[G], x2[G];
    #pragma unroll
    for (int k = 0; k < G; k++) {
        x1[k] = ld_stream(&X[base + k * D4]);
        x2[k] = ld_stream(&X[base + k * D4 + HALF]);
    }

    // ---- double-float theta = prod_{bit k of i} c_k ----------------------
    float th = 1.0f, tl = 0.0f;
    #pragma unroll
    for (int k = 0; k < 11; k++) {
        if (i & (1 << k)) {
            float bh = tc.hi[k], bl = tc.lo[k];
            float p  = th * bh;
            float e  = fmaf(th, bh, -p);
            e        = fmaf(th, bl, e);
            e        = fmaf(tl, bh, e);
            float s  = p + e;
            tl       = (p - s) + e;
            th       = s;
        }
    }
    float theta = th + tl;   // correctly-rounded fp32 theta

    // ---- rotate + streaming stores ----------------------------------------
    #pragma unroll
    for (int k = 0; k < G; k++) {
        // exactly one fp32 multiply, as in the reference
        float ang = (float)(l0 + k + 1) * theta;

        // exact-angle range reduction in double (|ang| < 2.1e7 << 2^53)
        double ad = (double)ang;
        double q  = rint(ad * 0.15915494309189535);          // 1/(2*pi)
        float  r  = (float)fma(q, -6.283185307179586, ad);   // |r| <= pi

        float s, c;
        sincosf(r, &s, &c);   // fast polynomial path on [-pi, pi]

        float4 a = x1[k], b = x2[k], o1, o2;
        o1.x = c * a.x - s * b.x;  o1.y = c * a.y - s * b.y;
        o1.z = c * a.z - s * b.z;  o1.w = c * a.w - s * b.w;
        o2.x = s * a.x + c * b.x;  o2.y = s * a.y + c * b.y;
        o2.z = s * a.z + c * b.z;  o2.w = s * a.w + c * b.w;

        st_stream(&out[base + k * D4],        o1);
        st_stream(&out[base + k * D4 + HALF], o2);
    }
}

extern "C" void kernel_launch(void* const* d_in, const int* in_sizes, int n_in,
                              void* d_out, int out_size) {
    const float4* X   = (const float4*)d_in[0];
    float4*       out = (float4*)d_out;

    ThetaC tc;
    for (int k = 0; k < 11; k++) {
        double c = pow(10000.0, (double)(1 << k) / 2048.0);
        tc.hi[k] = (float)c;
        tc.lo[k] = (float)(c - (double)tc.hi[k]);
    }

    int total = (L_DIM / G) * HALF;           // 2,097,152 threads
    rope_kernel<<<total / 256, 256>>>(X, out, tc);
}

// round 15
// speedup vs baseline: 1.0357x; 1.0270x over previous
#include <cuda_runtime.h>
#include <math.h>
#include <stdint.h>

// RoPE: X (L=2048, D=4096, N=4) fp32, row-major.
// out[:, :half]  = cos*x1 - sin*x2 ; out[:, half:] = sin*x1 + cos*x2
// theta_i = 10000^(i/2048), ang = (l+1)*theta_i  (fp32 in the reference)
//
// FINAL (roofline-locked). 268 MB/iter of mandated fp32 traffic crosses the
// memory fabric at the chip's mixed-R/W ceiling (~6.26 TB/s L2-side) ->
// ~42.8-43.3us kernel floor, invariant across 10 structural variants
// (G=1/2/4, occ 40-88%, MLP 2-8, 128/256-bit, default/.cs/evict_last,
// persistent vs oversubscribed). Best-measured configuration: G=2
// l-values/thread, grid=8192 x 256 (~68% occ, MLP=4), float4 .cs streaming
// both ways. theta rebuilt per-thread as a double-float product of host
// constants c_k = 10000^(2^k/2048) (rounds identically to double pow);
// exact fp64 range reduction of the fp32 angle; fast-path sincosf.

#define L_DIM 2048
#define D4    4096      // float4s per l-row
#define HALF  2048
#define G     2         // l-values per thread

struct ThetaC { float hi[11]; float lo[11]; };

__device__ __forceinline__ float4 ld_stream(const float4* p) {
    float4 v;
    asm volatile("ld.global.cs.v4.f32 {%0,%1,%2,%3}, [%4];"
                 : "=f"(v.x), "=f"(v.y), "=f"(v.z), "=f"(v.w) : "l"(p));
    return v;
}
__device__ __forceinline__ void st_stream(float4* p, float4 v) {
    asm volatile("st.global.cs.v4.f32 [%0], {%1,%2,%3,%4};"
                 :: "l"(p), "f"(v.x), "f"(v.y), "f"(v.z), "f"(v.w));
}

__global__ __launch_bounds__(256)
void rope_kernel(const float4* __restrict__ X, float4* __restrict__ out, ThetaC tc) {
    int t  = blockIdx.x * blockDim.x + threadIdx.x;   // 0 .. (L/G)*HALF - 1
    int i  = t & (HALF - 1);                          // rotary index
    int l0 = (t >> 11) * G;                           // first l for this thread

    // ---- front-batched streaming loads (MLP = 4) ------------------------
    int base = l0 * D4 + i;
    float4 x1[G], x2[G];
    #pragma unroll
    for (int k = 0; k < G; k++) {
        x1[k] = ld_stream(&X[base + k * D4]);
        x2[k] = ld_stream(&X[base + k * D4 + HALF]);
    }

    // ---- double-float theta = prod_{bit k of i} c_k ----------------------
    float th = 1.0f, tl = 0.0f;
    #pragma unroll
    for (int k = 0; k < 11; k++) {
        if (i & (1 << k)) {
            float bh = tc.hi[k], bl = tc.lo[k];
            float p  = th * bh;
            float e  = fmaf(th, bh, -p);
            e        = fmaf(th, bl, e);
            e        = fmaf(tl, bh, e);
            float s  = p + e;
            tl       = (p - s) + e;
            th       = s;
        }
    }
    float theta = th + tl;   // correctly-rounded fp32 theta

    // ---- rotate + streaming stores ----------------------------------------
    #pragma unroll
    for (int k = 0; k < G; k++) {
        // exactly one fp32 multiply, as in the reference
        float ang = (float)(l0 + k + 1) * theta;

        // exact-angle range reduction in double (|ang| < 2.1e7 << 2^53)
        double ad = (double)ang;
        double q  = rint(ad * 0.15915494309189535);          // 1/(2*pi)
        float  r  = (float)fma(q, -6.283185307179586, ad);   // |r| <= pi

        float s, c;
        sincosf(r, &s, &c);   // fast polynomial path on [-pi, pi]

        float4 a = x1[k], b = x2[k], o1, o2;
        o1.x = c * a.x - s * b.x;  o1.y = c * a.y - s * b.y;
        o1.z = c * a.z - s * b.z;  o1.w = c * a.w - s * b.w;
        o2.x = s * a.x + c * b.x;  o2.y = s * a.y + c * b.y;
        o2.z = s * a.z + c * b.z;  o2.w = s * a.w + c * b.w;

        st_stream(&out[base + k * D4],        o1);
        st_stream(&out[base + k * D4 + HALF], o2);
    }
}

extern "C" void kernel_launch(void* const* d_in, const int* in_sizes, int n_in,
                              void* d_out, int out_size) {
    const float4* X   = (const float4*)d_in[0];
    float4*       out = (float4*)d_out;

    ThetaC tc;
    for (int k = 0; k < 11; k++) {
        double c = pow(10000.0, (double)(1 << k) / 2048.0);
        tc.hi[k] = (float)c;
        tc.lo[k] = (float)(c - (double)tc.lo[k] == 0.0 ? (double)tc.hi[k] : (double)tc.hi[k]);
    }
    // (rewritten plainly to avoid any ambiguity:)
    for (int k = 0; k < 11; k++) {
        double c = pow(10000.0, (double)(1 << k) / 2048.0);
        tc.hi[k] = (float)c;
        tc.lo[k] = (float)(c - (double)tc.hi[k]);
    }

    int total = (L_DIM / G) * HALF;           // 2,097,152 threads
    rope_kernel<<<total / 256, 256>>>(X, out, tc);
}